// round 13
// baseline (speedup 1.0000x reference)
#include <cuda_runtime.h>
#include <cuda_fp16.h>
#include <cstdint>

// Problem shape (fixed): B=32, Q=512, K=512, D=1024, fp32.
// Inputs: queries f32[B,Q,D], keys f32[B,K,D], temperature f32[], bias f32[]
// Output: attn f32[B,Q,K] then confidence f32[B,Q].
//
// GEMM via 2-product fp16 "Karatsuba" split on mma.sync (HMMA, 16 cyc/SMSP
// issue rate measured R7/R8/R10):
//   h = fp16(x), l = x-h, v = fp16(h + 128*l)
//   P1 = h.h', P2 = v.v'   ->   x.x' ~= P1 + (P2-P1)/128   (meas. 3.5e-5)
// Occupancy 2 is load-bearing (R10 regression at occ 1): CTA tile 128x64,
// 256 threads, 64 acc regs -> ~116 regs/thread, 2 CTAs/SM.

#define BATCH 32
#define QDIM 512
#define KDIM 512
#define DDIM 1024

#define TM 128
#define TN 64
#define CK 16                    // k floats per stage
#define NST (DDIM / CK)          // 64 stages
#define LAMBDA 128.0f
#define INV_LAMBDA (1.0f / 128.0f)

// ---------------- PTX helpers ----------------
__device__ __forceinline__ uint32_t smem_u32(const void* p) {
    uint32_t a;
    asm("{ .reg .u64 t; cvta.to.shared.u64 t, %1; cvt.u32.u64 %0, t; }"
        : "=r"(a) : "l"(p));
    return a;
}

#define LDSM4(r0, r1, r2, r3, addr)                                        \
    asm volatile("ldmatrix.sync.aligned.m8n8.x4.shared.b16 "               \
                 "{%0, %1, %2, %3}, [%4];"                                 \
                 : "=r"(r0), "=r"(r1), "=r"(r2), "=r"(r3) : "r"(addr))

#define STS128(addr, r0, r1, r2, r3)                                       \
    asm volatile("st.shared.v4.b32 [%0], {%1, %2, %3, %4};"                \
                 :: "r"(addr), "r"(r0), "r"(r1), "r"(r2), "r"(r3) : "memory")

#define MMAF16(c, a0, a1, a2, a3, b0, b1)                                  \
    asm volatile("mma.sync.aligned.m16n8k16.row.col.f32.f16.f16.f32 "      \
                 "{%0, %1, %2, %3}, {%4, %5, %6, %7}, {%8, %9}, "          \
                 "{%0, %1, %2, %3};"                                       \
                 : "+f"((c)[0]), "+f"((c)[1]), "+f"((c)[2]), "+f"((c)[3])  \
                 : "r"(a0), "r"(a1), "r"(a2), "r"(a3), "r"(b0), "r"(b1))

// h = fp16(x); v = fp16(h + 128*(x-h)); packed as half2 pairs.
__device__ __forceinline__ void cvt2(float x, float y,
                                     uint32_t& h, uint32_t& v) {
    __half hx = __float2half_rn(x), hy = __float2half_rn(y);
    float fx = __half2float(hx),    fy = __half2float(hy);
    float vx = fmaf(LAMBDA, x - fx, fx);
    float vy = fmaf(LAMBDA, y - fy, fy);
    __half2 hh = __halves2half2(hx, hy);
    __half2 vv = __floats2half2_rn(vx, vy);
    h = *reinterpret_cast<uint32_t*>(&hh);
    v = *reinterpret_cast<uint32_t*>(&vv);
}

// Swizzled byte offset: row r, 16-byte chunk c (0..1), 32B rows.
__device__ __forceinline__ uint32_t swz(int r, int c) {
    return (uint32_t)(r * 32 + ((c ^ ((r >> 2) & 1)) << 4));
}

// ---------------------------------------------------------------------------
// GEMM: logits = Q*K^T, 2-product fp16 split; key mask -> -inf.
// CTA 128x64, 256 threads, warps 4(M) x 2(N), warp tile 32x32.
// Double-buffered smem, one barrier per stage, occupancy 2.
// ---------------------------------------------------------------------------
__global__ __launch_bounds__(256, 2)
void gemm_f16k_kernel(const float* __restrict__ Qg,
                      const float* __restrict__ Kg,
                      float* __restrict__ Cg) {
    __shared__ __align__(128) uint8_t sAh[2][4096], sAv[2][4096];   // 128 rows
    __shared__ __align__(128) uint8_t sBh[2][2048], sBv[2][2048];   // 64 rows
    __shared__ float maskv[TN];

    const int tid  = threadIdx.x;
    const int lane = tid & 31;
    const int wid  = tid >> 5;         // 0..7
    const int wm   = wid & 3;          // M
    const int wn   = wid >> 2;         // N (0..1)

    const int bn = blockIdx.x * TN;
    const int bm = blockIdx.y * TM;
    const int b  = blockIdx.z;

    const float* A  = Qg + (size_t)b * QDIM * DDIM;
    const float* Bp = Kg + (size_t)b * KDIM * DDIM;
    float*       C  = Cg + (size_t)b * QDIM * KDIM;

    if (tid < TN)
        maskv[tid] = (Bp[(size_t)(bn + tid) * DDIM] == 0.0f) ? 1.0f : 0.0f;

    // ---- producer mapping ----
    // A: all 256 threads, row tid>>1, chunk tid&1 (8 floats each).
    // B: warps 0-3 (tid<128) additionally load row tid>>1 (0..63), chunk tid&1.
    const int prA = tid >> 1, phA = tid & 1;
    const uint32_t soA = swz(prA, phA);
    const uint32_t stAh = smem_u32(sAh) + soA;
    const uint32_t stAv = smem_u32(sAv) + soA;
    const float* gA = A + (size_t)(bm + prA) * DDIM + phA * 8;

    const bool doB = (tid < 128);
    const int prB = (tid & 127) >> 1, phB = tid & 1;
    const uint32_t soB = swz(prB, phB);
    const uint32_t stBh = smem_u32(sBh) + soB;
    const uint32_t stBv = smem_u32(sBv) + soB;
    const float* gB = Bp + (size_t)(bn + prB) * DDIM + phB * 8;

    // ---- ldmatrix addresses (buffer 0; +4096/+2048 selects buffer 1) ----
    uint32_t lmA, lmB;
    {
        int r = wm * 32 + (lane & 15);
        int c = lane >> 4;
        lmA = swz(r, c);
    }
    {
        int r = wn * 32 + (lane & 7) + ((lane >> 4) << 3);
        int c = (lane >> 3) & 1;
        lmB = swz(r, c);
    }
    const uint32_t aAh = smem_u32(sAh) + lmA;
    const uint32_t aAv = smem_u32(sAv) + lmA;
    const uint32_t aBh = smem_u32(sBh) + lmB;
    const uint32_t aBv = smem_u32(sBv) + lmB;

    float acc1[2][4][4], acc2[2][4][4];
    #pragma unroll
    for (int i = 0; i < 2; ++i)
        #pragma unroll
        for (int j = 0; j < 4; ++j)
            #pragma unroll
            for (int k = 0; k < 4; ++k) { acc1[i][j][k] = 0.0f; acc2[i][j][k] = 0.0f; }

    // ---- prologue: stage 0 -> buf0; prefetch stage 1 ----
    float4 va0 = *(const float4*)gA;
    float4 va1 = *(const float4*)(gA + 4);
    float4 vb0, vb1;
    if (doB) { vb0 = *(const float4*)gB; vb1 = *(const float4*)(gB + 4); }
    {
        uint32_t h0, h1, h2, h3, w0, w1, w2, w3;
        cvt2(va0.x, va0.y, h0, w0); cvt2(va0.z, va0.w, h1, w1);
        cvt2(va1.x, va1.y, h2, w2); cvt2(va1.z, va1.w, h3, w3);
        STS128(stAh, h0, h1, h2, h3);
        STS128(stAv, w0, w1, w2, w3);
        if (doB) {
            cvt2(vb0.x, vb0.y, h0, w0); cvt2(vb0.z, vb0.w, h1, w1);
            cvt2(vb1.x, vb1.y, h2, w2); cvt2(vb1.z, vb1.w, h3, w3);
            STS128(stBh, h0, h1, h2, h3);
            STS128(stBv, w0, w1, w2, w3);
        }
    }
    gA += CK;
    va0 = *(const float4*)gA;
    va1 = *(const float4*)(gA + 4);
    if (doB) {
        gB += CK;
        vb0 = *(const float4*)gB;
        vb1 = *(const float4*)(gB + 4);
    }
    __syncthreads();

    for (int s = 0; s < NST; ++s) {
        const uint32_t rdA = (uint32_t)(s & 1) * 4096;
        const uint32_t wrA = 4096 - rdA;
        const uint32_t rdB = (uint32_t)(s & 1) * 2048;
        const uint32_t wrB = 2048 - rdB;

        // ---- A fragments (both products) from the read buffer ----
        uint32_t Ah[2][4], Av[2][4];
        LDSM4(Ah[0][0], Ah[0][1], Ah[0][2], Ah[0][3], aAh + rdA);
        LDSM4(Ah[1][0], Ah[1][1], Ah[1][2], Ah[1][3], aAh + rdA + 512);
        LDSM4(Av[0][0], Av[0][1], Av[0][2], Av[0][3], aAv + rdA);
        LDSM4(Av[1][0], Av[1][1], Av[1][2], Av[1][3], aAv + rdA + 512);

        // ---- split + store NEXT stage into the write buffer ----
        if (s + 1 < NST) {
            uint32_t h0, h1, h2, h3, w0, w1, w2, w3;
            cvt2(va0.x, va0.y, h0, w0); cvt2(va0.z, va0.w, h1, w1);
            cvt2(va1.x, va1.y, h2, w2); cvt2(va1.z, va1.w, h3, w3);
            STS128(stAh + wrA, h0, h1, h2, h3);
            STS128(stAv + wrA, w0, w1, w2, w3);
            if (doB) {
                cvt2(vb0.x, vb0.y, h0, w0); cvt2(vb0.z, vb0.w, h1, w1);
                cvt2(vb1.x, vb1.y, h2, w2); cvt2(vb1.z, vb1.w, h3, w3);
                STS128(stBh + wrB, h0, h1, h2, h3);
                STS128(stBv + wrB, w0, w1, w2, w3);
            }
        }
        // ---- prefetch stage s+2 from gmem ----
        if (s + 2 < NST) {
            gA += CK;
            va0 = *(const float4*)gA;
            va1 = *(const float4*)(gA + 4);
            if (doB) {
                gB += CK;
                vb0 = *(const float4*)gB;
                vb1 = *(const float4*)(gB + 4);
            }
        }

        // ---- 4 B-LDSM + 16 HMMA ----
        uint32_t Bh[8], Bv[8];
        LDSM4(Bh[0], Bh[1], Bh[2], Bh[3], aBh + rdB);
        LDSM4(Bh[4], Bh[5], Bh[6], Bh[7], aBh + rdB + 512);
        LDSM4(Bv[0], Bv[1], Bv[2], Bv[3], aBv + rdB);
        LDSM4(Bv[4], Bv[5], Bv[6], Bv[7], aBv + rdB + 512);

        #pragma unroll
        for (int mi = 0; mi < 2; ++mi) {
            #pragma unroll
            for (int nj = 0; nj < 4; ++nj) {
                MMAF16(acc1[mi][nj], Ah[mi][0], Ah[mi][1], Ah[mi][2], Ah[mi][3],
                       Bh[2 * nj], Bh[2 * nj + 1]);
                MMAF16(acc2[mi][nj], Av[mi][0], Av[mi][1], Av[mi][2], Av[mi][3],
                       Bv[2 * nj], Bv[2 * nj + 1]);
            }
        }
        __syncthreads();
    }

    // ---- epilogue: combine P1 + (P2-P1)/lambda, mask, store ----
    const float NEG_INF = __int_as_float(0xff800000);
    const int mrow = bm + wm * 32 + (lane >> 2);
    const int ncl  = wn * 32 + (lane & 3) * 2;
    #pragma unroll
    for (int mi = 0; mi < 2; ++mi) {
        #pragma unroll
        for (int nj = 0; nj < 4; ++nj) {
            const int nc = ncl + nj * 8;
            const float m0 = maskv[nc];
            const float m1 = maskv[nc + 1];
            const float* p1 = acc1[mi][nj];
            const float* p2 = acc2[mi][nj];
            float r0 = fmaf(p2[0] - p1[0], INV_LAMBDA, p1[0]);
            float r1 = fmaf(p2[1] - p1[1], INV_LAMBDA, p1[1]);
            float r2 = fmaf(p2[2] - p1[2], INV_LAMBDA, p1[2]);
            float r3 = fmaf(p2[3] - p1[3], INV_LAMBDA, p1[3]);
            float2 o0, o1;
            o0.x = (m0 != 0.0f) ? NEG_INF : r0;
            o0.y = (m1 != 0.0f) ? NEG_INF : r1;
            o1.x = (m0 != 0.0f) ? NEG_INF : r2;
            o1.y = (m1 != 0.0f) ? NEG_INF : r3;
            float* base = C + (size_t)(mrow + mi * 16) * KDIM + bn + nc;
            *(float2*)base              = o0;
            *(float2*)(base + 8 * KDIM) = o1;
        }
    }
}

// ---------------------------------------------------------------------------
// Softmax + confidence
// ---------------------------------------------------------------------------
__global__ __launch_bounds__(128)
void softmax_conf_kernel(const float* __restrict__ tptr,
                         const float* __restrict__ bptr,
                         float* __restrict__ out) {
    __shared__ float red[4];
    const int row = blockIdx.x;
    float* lr = out + (size_t)row * KDIM;
    const int tid = threadIdx.x;

    float4 v = *(const float4*)(lr + tid * 4);

    float m = fmaxf(fmaxf(v.x, v.y), fmaxf(v.z, v.w));
    #pragma unroll
    for (int o = 16; o > 0; o >>= 1)
        m = fmaxf(m, __shfl_xor_sync(0xffffffffu, m, o));
    if ((tid & 31) == 0) red[tid >> 5] = m;
    __syncthreads();
    m = fmaxf(fmaxf(red[0], red[1]), fmaxf(red[2], red[3]));
    __syncthreads();

    float e0 = __expf(v.x - m);
    float e1 = __expf(v.y - m);
    float e2 = __expf(v.z - m);
    float e3 = __expf(v.w - m);
    float s = (e0 + e1) + (e2 + e3);
    #pragma unroll
    for (int o = 16; o > 0; o >>= 1)
        s += __shfl_xor_sync(0xffffffffu, s, o);
    if ((tid & 31) == 0) red[tid >> 5] = s;
    __syncthreads();
    s = (red[0] + red[1]) + (red[2] + red[3]);

    const float inv = 1.0f / s;
    *(float4*)(lr + tid * 4) = make_float4(e0 * inv, e1 * inv, e2 * inv, e3 * inv);

    if (tid == 0) {
        const float lse = m + logf(s);
        const float x = (lse + bptr[0]) * tptr[0];
        out[(size_t)BATCH * QDIM * KDIM + row] = 1.0f / (1.0f + __expf(-x));
    }
}

// ---------------------------------------------------------------------------
extern "C" void kernel_launch(void* const* d_in, const int* in_sizes, int n_in,
                              void* d_out, int out_size) {
    const float* q    = (const float*)d_in[0];
    const float* k    = (const float*)d_in[1];
    const float* temp = (const float*)d_in[2];
    const float* bias = (const float*)d_in[3];
    float* out = (float*)d_out;

    dim3 ggrid(KDIM / TN, QDIM / TM, BATCH);   // (8, 4, 32) = 1024 CTAs
    gemm_f16k_kernel<<<ggrid, 256>>>(q, k, out);

    softmax_conf_kernel<<<BATCH * QDIM, 128>>>(temp, bias, out);
}

// round 14
// speedup vs baseline: 1.1685x; 1.1685x over previous
#include <cuda_runtime.h>
#include <cuda_bf16.h>
#include <cstdint>

// Problem shape (fixed): B=32, Q=512, K=512, D=1024, fp32.
// Inputs: queries f32[B,Q,D], keys f32[B,K,D], temperature f32[], bias f32[]
// Output: attn f32[B,Q,K] then confidence f32[B,Q].
//
// GEMM: error-free bf16 2-term split, 3 MMA products (hi*hi + hi*lo + lo*hi)
// on mma.sync m16n8k16 (measured 16 cyc/SMSP issue rate — the binding
// resource). This round: quad-buffered k-chunks, TWO chunks (96 HMMA) per
// __syncthreads to halve barrier overhead; held-prefetch registers recycled
// mid-iteration so occupancy stays at 2.

#define BATCH 32
#define QDIM 512
#define KDIM 512
#define DDIM 1024

#define TM 128
#define TN 128
#define NCHUNK 64                 // 64 chunks of k=16 floats

// Dynamic smem layout: 4 slots per operand tile (4KB each)
#define SM_AH 0
#define SM_AL 16384
#define SM_BH 32768
#define SM_BL 49152
#define SM_MASK 65536
#define SMEM_TOTAL (65536 + 512)

// ---------------- PTX helpers ----------------
__device__ __forceinline__ uint32_t smem_u32(const void* p) {
    uint32_t a;
    asm("{ .reg .u64 t; cvta.to.shared.u64 t, %1; cvt.u32.u64 %0, t; }"
        : "=r"(a) : "l"(p));
    return a;
}

#define LDSM4(r0, r1, r2, r3, addr)                                        \
    asm volatile("ldmatrix.sync.aligned.m8n8.x4.shared.b16 "               \
                 "{%0, %1, %2, %3}, [%4];"                                 \
                 : "=r"(r0), "=r"(r1), "=r"(r2), "=r"(r3) : "r"(addr))

#define STS128(addr, r0, r1, r2, r3)                                       \
    asm volatile("st.shared.v4.b32 [%0], {%1, %2, %3, %4};"                \
                 :: "r"(addr), "r"(r0), "r"(r1), "r"(r2), "r"(r3) : "memory")

#define MMA16816(c, a0, a1, a2, a3, b0, b1)                                \
    asm volatile("mma.sync.aligned.m16n8k16.row.col.f32.bf16.bf16.f32 "    \
                 "{%0, %1, %2, %3}, {%4, %5, %6, %7}, {%8, %9}, "          \
                 "{%0, %1, %2, %3};"                                       \
                 : "+f"((c)[0]), "+f"((c)[1]), "+f"((c)[2]), "+f"((c)[3])  \
                 : "r"(a0), "r"(a1), "r"(a2), "r"(a3), "r"(b0), "r"(b1))

// Split (x, y) into bf16 hi pair and bf16 lo pair (packed 2x16-bit words).
__device__ __forceinline__ void split2(float x, float y,
                                       uint32_t& h, uint32_t& l) {
    __nv_bfloat162 hh = __floats2bfloat162_rn(x, y);
    float rx = x - __bfloat162float(hh.x);
    float ry = y - __bfloat162float(hh.y);
    __nv_bfloat162 ll = __floats2bfloat162_rn(rx, ry);
    h = reinterpret_cast<uint32_t&>(hh);
    l = reinterpret_cast<uint32_t&>(ll);
}

// Swizzled byte offset: row r (0..127), 16-byte chunk c (0..1); 32B rows.
__device__ __forceinline__ uint32_t swz(int r, int c) {
    return (uint32_t)(r * 32 + ((c ^ ((r >> 2) & 1)) << 4));
}

// ---------------------------------------------------------------------------
// GEMM: logits = Q*K^T via 3x bf16 mma.sync split; key mask -> -inf.
// CTA 128x128, 256 threads, warps 4(M) x 2(N), warp tile 32x64.
// Quad-buffered k16 chunks, one barrier per 2 chunks, occupancy 2.
// ---------------------------------------------------------------------------
__global__ __launch_bounds__(256, 2)
void gemm_bf16split_kernel(const float* __restrict__ Qg,
                           const float* __restrict__ Kg,
                           float* __restrict__ Cg) {
    extern __shared__ __align__(128) uint8_t smem[];
    const uint32_t sb = smem_u32(smem);
    float* maskv = (float*)(smem + SM_MASK);

    const int tid  = threadIdx.x;
    const int lane = tid & 31;
    const int wid  = tid >> 5;
    const int wm   = wid & 3;          // 0..3  (M)
    const int wn   = wid >> 2;         // 0..1  (N)

    const int bn = blockIdx.x * TN;
    const int bm = blockIdx.y * TM;
    const int b  = blockIdx.z;

    const float* A  = Qg + (size_t)b * QDIM * DDIM;
    const float* Bp = Kg + (size_t)b * KDIM * DDIM;
    float*       C  = Cg + (size_t)b * QDIM * KDIM;

    if (tid < TN)
        maskv[tid] = (Bp[(size_t)(bn + tid) * DDIM] == 0.0f) ? 1.0f : 0.0f;

    // ---- producer mapping: thread -> (row, k-half); 8 floats per operand ----
    const int pr = tid >> 1;           // 0..127
    const int ph = tid & 1;            // 16B k-chunk within a 16-float chunk
    const uint32_t so = swz(pr, ph);
    const uint32_t stAh = sb + SM_AH + so;
    const uint32_t stAl = sb + SM_AL + so;
    const uint32_t stBh = sb + SM_BH + so;
    const uint32_t stBl = sb + SM_BL + so;
    const float* gA = A  + (size_t)(bm + pr) * DDIM + ph * 8;
    const float* gB = Bp + (size_t)(bn + pr) * DDIM + ph * 8;

    // ---- ldmatrix addresses (slot 0 base; +slot*4096 selects slot) ----
    uint32_t lmA, lmB;
    {
        int r = wm * 32 + (lane & 15);
        int c = lane >> 4;
        lmA = swz(r, c);
    }
    {
        int r = wn * 64 + (lane & 7) + ((lane >> 4) << 3);
        int c = (lane >> 3) & 1;
        lmB = swz(r, c);
    }
    const uint32_t aAh = sb + SM_AH + lmA;
    const uint32_t aAl = sb + SM_AL + lmA;
    const uint32_t aBh = sb + SM_BH + lmB;
    const uint32_t aBl = sb + SM_BL + lmB;

    float acc[2][8][4];
    #pragma unroll
    for (int i = 0; i < 2; ++i)
        #pragma unroll
        for (int j = 0; j < 8; ++j)
            #pragma unroll
            for (int k = 0; k < 4; ++k) acc[i][j][k] = 0.0f;

    float4 va0, va1, vb0, vb1;         // the single held prefetch set

    // load chunk c into the held registers
    #define LDG_CHUNK(c) do {                                              \
        const float* _pa = gA + (c) * 16;                                  \
        const float* _pb = gB + (c) * 16;                                  \
        va0 = *(const float4*)_pa;  va1 = *(const float4*)(_pa + 4);       \
        vb0 = *(const float4*)_pb;  vb1 = *(const float4*)(_pb + 4);       \
    } while (0)

    // split + store the held registers into slot q (byte offset q*4096)
    #define STS_CHUNK(q) do {                                              \
        const uint32_t _o = (uint32_t)(q) * 4096u;                         \
        uint32_t h0, h1, h2, h3, l0, l1, l2, l3;                           \
        split2(va0.x, va0.y, h0, l0); split2(va0.z, va0.w, h1, l1);        \
        split2(va1.x, va1.y, h2, l2); split2(va1.z, va1.w, h3, l3);        \
        STS128(stAh + _o, h0, h1, h2, h3);                                 \
        STS128(stAl + _o, l0, l1, l2, l3);                                 \
        split2(vb0.x, vb0.y, h0, l0); split2(vb0.z, vb0.w, h1, l1);        \
        split2(vb1.x, vb1.y, h2, l2); split2(vb1.z, vb1.w, h3, l3);        \
        STS128(stBh + _o, h0, h1, h2, h3);                                 \
        STS128(stBl + _o, l0, l1, l2, l3);                                 \
    } while (0)

    // 4 A-LDSM + 8 B-LDSM + 48 HMMA on slot q
    #define MMA_SLOT(q) do {                                               \
        const uint32_t _o = (uint32_t)(q) * 4096u;                         \
        uint32_t Ah[2][4], Al[2][4];                                       \
        LDSM4(Ah[0][0], Ah[0][1], Ah[0][2], Ah[0][3], aAh + _o);           \
        LDSM4(Ah[1][0], Ah[1][1], Ah[1][2], Ah[1][3], aAh + _o + 512);     \
        LDSM4(Al[0][0], Al[0][1], Al[0][2], Al[0][3], aAl + _o);           \
        LDSM4(Al[1][0], Al[1][1], Al[1][2], Al[1][3], aAl + _o + 512);     \
        _Pragma("unroll")                                                  \
        for (int q4 = 0; q4 < 4; ++q4) {                                   \
            uint32_t Bh[4], Bl[4];                                         \
            LDSM4(Bh[0], Bh[1], Bh[2], Bh[3], aBh + _o + q4 * 512);        \
            LDSM4(Bl[0], Bl[1], Bl[2], Bl[3], aBl + _o + q4 * 512);        \
            _Pragma("unroll")                                              \
            for (int mi = 0; mi < 2; ++mi) {                               \
                float* c0 = acc[mi][2 * q4];                               \
                float* c1 = acc[mi][2 * q4 + 1];                           \
                MMA16816(c0, Ah[mi][0], Ah[mi][1], Ah[mi][2], Ah[mi][3], Bh[0], Bh[1]); \
                MMA16816(c0, Ah[mi][0], Ah[mi][1], Ah[mi][2], Ah[mi][3], Bl[0], Bl[1]); \
                MMA16816(c0, Al[mi][0], Al[mi][1], Al[mi][2], Al[mi][3], Bh[0], Bh[1]); \
                MMA16816(c1, Ah[mi][0], Ah[mi][1], Ah[mi][2], Ah[mi][3], Bh[2], Bh[3]); \
                MMA16816(c1, Ah[mi][0], Ah[mi][1], Ah[mi][2], Ah[mi][3], Bl[2], Bl[3]); \
                MMA16816(c1, Al[mi][0], Al[mi][1], Al[mi][2], Al[mi][3], Bh[2], Bh[3]); \
            }                                                              \
        }                                                                  \
    } while (0)

    // ---- prologue: chunks 0,1 into slots 0,1; chunk 2 held ----
    LDG_CHUNK(0); STS_CHUNK(0);
    LDG_CHUNK(1); STS_CHUNK(1);
    LDG_CHUNK(2);
    __syncthreads();

    // ---- main loop: 2 chunks per barrier ----
    for (int s = 0; s < NCHUNK / 2; ++s) {
        const int c2 = 2 * s + 2;
        if (c2 < NCHUNK)     STS_CHUNK(c2 & 3);        // held = chunk 2s+2
        if (c2 + 1 < NCHUNK) LDG_CHUNK(c2 + 1);        // -> chunk 2s+3
        MMA_SLOT((2 * s) & 3);
        if (c2 + 1 < NCHUNK) STS_CHUNK((c2 + 1) & 3);
        if (c2 + 2 < NCHUNK) LDG_CHUNK(c2 + 2);        // held for next iter
        MMA_SLOT((2 * s + 1) & 3);
        __syncthreads();
    }

    // ---- epilogue: apply key mask, write C ----
    const float NEG_INF = __int_as_float(0xff800000);
    const int mrow = bm + wm * 32 + (lane >> 2);
    const int ncl  = wn * 64 + (lane & 3) * 2;
    #pragma unroll
    for (int mi = 0; mi < 2; ++mi) {
        #pragma unroll
        for (int ni = 0; ni < 8; ++ni) {
            const int nc = ncl + ni * 8;
            const float m0 = maskv[nc];
            const float m1 = maskv[nc + 1];
            const float* c = acc[mi][ni];
            float2 v0, v1;
            v0.x = (m0 != 0.0f) ? NEG_INF : c[0];
            v0.y = (m1 != 0.0f) ? NEG_INF : c[1];
            v1.x = (m0 != 0.0f) ? NEG_INF : c[2];
            v1.y = (m1 != 0.0f) ? NEG_INF : c[3];
            float* base = C + (size_t)(mrow + mi * 16) * KDIM + bn + nc;
            *(float2*)base              = v0;
            *(float2*)(base + 8 * KDIM) = v1;
        }
    }
    #undef LDG_CHUNK
    #undef STS_CHUNK
    #undef MMA_SLOT
}

// ---------------------------------------------------------------------------
// Softmax + confidence
// ---------------------------------------------------------------------------
__global__ __launch_bounds__(128)
void softmax_conf_kernel(const float* __restrict__ tptr,
                         const float* __restrict__ bptr,
                         float* __restrict__ out) {
    __shared__ float red[4];
    const int row = blockIdx.x;
    float* lr = out + (size_t)row * KDIM;
    const int tid = threadIdx.x;

    float4 v = *(const float4*)(lr + tid * 4);

    float m = fmaxf(fmaxf(v.x, v.y), fmaxf(v.z, v.w));
    #pragma unroll
    for (int o = 16; o > 0; o >>= 1)
        m = fmaxf(m, __shfl_xor_sync(0xffffffffu, m, o));
    if ((tid & 31) == 0) red[tid >> 5] = m;
    __syncthreads();
    m = fmaxf(fmaxf(red[0], red[1]), fmaxf(red[2], red[3]));
    __syncthreads();

    float e0 = __expf(v.x - m);
    float e1 = __expf(v.y - m);
    float e2 = __expf(v.z - m);
    float e3 = __expf(v.w - m);
    float s = (e0 + e1) + (e2 + e3);
    #pragma unroll
    for (int o = 16; o > 0; o >>= 1)
        s += __shfl_xor_sync(0xffffffffu, s, o);
    if ((tid & 31) == 0) red[tid >> 5] = s;
    __syncthreads();
    s = (red[0] + red[1]) + (red[2] + red[3]);

    const float inv = 1.0f / s;
    *(float4*)(lr + tid * 4) = make_float4(e0 * inv, e1 * inv, e2 * inv, e3 * inv);

    if (tid == 0) {
        const float lse = m + logf(s);
        const float x = (lse + bptr[0]) * tptr[0];
        out[(size_t)BATCH * QDIM * KDIM + row] = 1.0f / (1.0f + __expf(-x));
    }
}

// ---------------------------------------------------------------------------
extern "C" void kernel_launch(void* const* d_in, const int* in_sizes, int n_in,
                              void* d_out, int out_size) {
    const float* q    = (const float*)d_in[0];
    const float* k    = (const float*)d_in[1];
    const float* temp = (const float*)d_in[2];
    const float* bias = (const float*)d_in[3];
    float* out = (float*)d_out;

    cudaFuncSetAttribute(gemm_bf16split_kernel,
                         cudaFuncAttributeMaxDynamicSharedMemorySize, SMEM_TOTAL);

    dim3 ggrid(KDIM / TN, QDIM / TM, BATCH);   // (4, 4, 32) = 512 CTAs
    gemm_bf16split_kernel<<<ggrid, 256, SMEM_TOTAL>>>(q, k, out);

    softmax_conf_kernel<<<BATCH * QDIM, 128>>>(temp, bias, out);
}

// round 15
// speedup vs baseline: 1.1835x; 1.0129x over previous
#include <cuda_runtime.h>
#include <cuda_bf16.h>
#include <cstdint>

// Problem shape (fixed): B=32, Q=512, K=512, D=1024, fp32.
// Inputs: queries f32[B,Q,D], keys f32[B,K,D], temperature f32[], bias f32[]
// Output: attn f32[B,Q,K] then confidence f32[B,Q].
//
// GEMM: error-free bf16 2-term split, 3 MMA products (hi*hi + hi*lo + lo*hi)
// on mma.sync m16n8k16 (measured ~16 cyc/SMSP issue rate — the binding
// resource; kernel runs at ~100% of that model). This round: ring-6 k-chunk
// slots, THREE chunks per __syncthreads (21 barriers vs 32), zero-guard
// 6-chunk double-windows. Softmax: warp-per-row, no block barriers.

#define BATCH 32
#define QDIM 512
#define KDIM 512
#define DDIM 1024

#define TM 128
#define TN 128
#define NCHUNK 64                 // 64 chunks of k=16 floats

// Dynamic smem: 6 slots per operand tensor (4KB each slot)
#define SM_AH 0
#define SM_AL 24576
#define SM_BH 49152
#define SM_BL 73728
#define SM_MASK 98304
#define SMEM_TOTAL (98304 + 512)

// ---------------- PTX helpers ----------------
__device__ __forceinline__ uint32_t smem_u32(const void* p) {
    uint32_t a;
    asm("{ .reg .u64 t; cvta.to.shared.u64 t, %1; cvt.u32.u64 %0, t; }"
        : "=r"(a) : "l"(p));
    return a;
}

#define LDSM4(r0, r1, r2, r3, addr)                                        \
    asm volatile("ldmatrix.sync.aligned.m8n8.x4.shared.b16 "               \
                 "{%0, %1, %2, %3}, [%4];"                                 \
                 : "=r"(r0), "=r"(r1), "=r"(r2), "=r"(r3) : "r"(addr))

#define STS128(addr, r0, r1, r2, r3)                                       \
    asm volatile("st.shared.v4.b32 [%0], {%1, %2, %3, %4};"                \
                 :: "r"(addr), "r"(r0), "r"(r1), "r"(r2), "r"(r3) : "memory")

#define MMA16816(c, a0, a1, a2, a3, b0, b1)                                \
    asm volatile("mma.sync.aligned.m16n8k16.row.col.f32.bf16.bf16.f32 "    \
                 "{%0, %1, %2, %3}, {%4, %5, %6, %7}, {%8, %9}, "          \
                 "{%0, %1, %2, %3};"                                       \
                 : "+f"((c)[0]), "+f"((c)[1]), "+f"((c)[2]), "+f"((c)[3])  \
                 : "r"(a0), "r"(a1), "r"(a2), "r"(a3), "r"(b0), "r"(b1))

__device__ __forceinline__ void split2(float x, float y,
                                       uint32_t& h, uint32_t& l) {
    __nv_bfloat162 hh = __floats2bfloat162_rn(x, y);
    float rx = x - __bfloat162float(hh.x);
    float ry = y - __bfloat162float(hh.y);
    __nv_bfloat162 ll = __floats2bfloat162_rn(rx, ry);
    h = reinterpret_cast<uint32_t&>(hh);
    l = reinterpret_cast<uint32_t&>(ll);
}

// Swizzled byte offset: row r (0..127), 16-byte chunk c (0..1); 32B rows.
__device__ __forceinline__ uint32_t swz(int r, int c) {
    return (uint32_t)(r * 32 + ((c ^ ((r >> 2) & 1)) << 4));
}

// ---------------------------------------------------------------------------
// GEMM: logits = Q*K^T via 3x bf16 mma.sync split; key mask -> -inf.
// CTA 128x128, 256 threads, warps 4(M) x 2(N), warp tile 32x64.
// Ring-6 k16 slots, one barrier per 3 chunks, occupancy 2.
// ---------------------------------------------------------------------------
__global__ __launch_bounds__(256, 2)
void gemm_bf16split_kernel(const float* __restrict__ Qg,
                           const float* __restrict__ Kg,
                           float* __restrict__ Cg) {
    extern __shared__ __align__(128) uint8_t smem[];
    const uint32_t sb = smem_u32(smem);
    float* maskv = (float*)(smem + SM_MASK);

    const int tid  = threadIdx.x;
    const int lane = tid & 31;
    const int wid  = tid >> 5;
    const int wm   = wid & 3;          // 0..3  (M)
    const int wn   = wid >> 2;         // 0..1  (N)

    const int bn = blockIdx.x * TN;
    const int bm = blockIdx.y * TM;
    const int b  = blockIdx.z;

    const float* A  = Qg + (size_t)b * QDIM * DDIM;
    const float* Bp = Kg + (size_t)b * KDIM * DDIM;
    float*       C  = Cg + (size_t)b * QDIM * KDIM;

    if (tid < TN)
        maskv[tid] = (Bp[(size_t)(bn + tid) * DDIM] == 0.0f) ? 1.0f : 0.0f;

    // ---- producer mapping: thread -> (row, k-half); 8 floats per operand ----
    const int pr = tid >> 1;           // 0..127
    const int ph = tid & 1;
    const uint32_t so = swz(pr, ph);
    const uint32_t stAh = sb + SM_AH + so;
    const uint32_t stAl = sb + SM_AL + so;
    const uint32_t stBh = sb + SM_BH + so;
    const uint32_t stBl = sb + SM_BL + so;
    const float* gA = A  + (size_t)(bm + pr) * DDIM + ph * 8;
    const float* gB = Bp + (size_t)(bn + pr) * DDIM + ph * 8;

    // ---- ldmatrix addresses (slot 0 base; +slot*4096 selects slot) ----
    uint32_t lmA, lmB;
    {
        int r = wm * 32 + (lane & 15);
        int c = lane >> 4;
        lmA = swz(r, c);
    }
    {
        int r = wn * 64 + (lane & 7) + ((lane >> 4) << 3);
        int c = (lane >> 3) & 1;
        lmB = swz(r, c);
    }
    const uint32_t aAh = sb + SM_AH + lmA;
    const uint32_t aAl = sb + SM_AL + lmA;
    const uint32_t aBh = sb + SM_BH + lmB;
    const uint32_t aBl = sb + SM_BL + lmB;

    float acc[2][8][4];
    #pragma unroll
    for (int i = 0; i < 2; ++i)
        #pragma unroll
        for (int j = 0; j < 8; ++j)
            #pragma unroll
            for (int k = 0; k < 4; ++k) acc[i][j][k] = 0.0f;

    float4 va0, va1, vb0, vb1;         // the single held prefetch set

    #define LDG_CHUNK(c) do {                                              \
        const float* _pa = gA + (c) * 16;                                  \
        const float* _pb = gB + (c) * 16;                                  \
        va0 = *(const float4*)_pa;  va1 = *(const float4*)(_pa + 4);       \
        vb0 = *(const float4*)_pb;  vb1 = *(const float4*)(_pb + 4);       \
    } while (0)

    #define STS_CHUNK(q) do {                                              \
        const uint32_t _o = (uint32_t)(q) * 4096u;                         \
        uint32_t h0, h1, h2, h3, l0, l1, l2, l3;                           \
        split2(va0.x, va0.y, h0, l0); split2(va0.z, va0.w, h1, l1);        \
        split2(va1.x, va1.y, h2, l2); split2(va1.z, va1.w, h3, l3);        \
        STS128(stAh + _o, h0, h1, h2, h3);                                 \
        STS128(stAl + _o, l0, l1, l2, l3);                                 \
        split2(vb0.x, vb0.y, h0, l0); split2(vb0.z, vb0.w, h1, l1);        \
        split2(vb1.x, vb1.y, h2, l2); split2(vb1.z, vb1.w, h3, l3);        \
        STS128(stBh + _o, h0, h1, h2, h3);                                 \
        STS128(stBl + _o, l0, l1, l2, l3);                                 \
    } while (0)

    #define MMA_SLOT(q) do {                                               \
        const uint32_t _o = (uint32_t)(q) * 4096u;                         \
        uint32_t Ah[2][4], Al[2][4];                                       \
        LDSM4(Ah[0][0], Ah[0][1], Ah[0][2], Ah[0][3], aAh + _o);           \
        LDSM4(Ah[1][0], Ah[1][1], Ah[1][2], Ah[1][3], aAh + _o + 512);     \
        LDSM4(Al[0][0], Al[0][1], Al[0][2], Al[0][3], aAl + _o);           \
        LDSM4(Al[1][0], Al[1][1], Al[1][2], Al[1][3], aAl + _o + 512);     \
        _Pragma("unroll")                                                  \
        for (int q4 = 0; q4 < 4; ++q4) {                                   \
            uint32_t Bh[4], Bl[4];                                         \
            LDSM4(Bh[0], Bh[1], Bh[2], Bh[3], aBh + _o + q4 * 512);        \
            LDSM4(Bl[0], Bl[1], Bl[2], Bl[3], aBl + _o + q4 * 512);        \
            _Pragma("unroll")                                              \
            for (int mi = 0; mi < 2; ++mi) {                               \
                float* c0 = acc[mi][2 * q4];                               \
                float* c1 = acc[mi][2 * q4 + 1];                           \
                MMA16816(c0, Ah[mi][0], Ah[mi][1], Ah[mi][2], Ah[mi][3], Bh[0], Bh[1]); \
                MMA16816(c0, Ah[mi][0], Ah[mi][1], Ah[mi][2], Ah[mi][3], Bl[0], Bl[1]); \
                MMA16816(c0, Al[mi][0], Al[mi][1], Al[mi][2], Al[mi][3], Bh[0], Bh[1]); \
                MMA16816(c1, Ah[mi][0], Ah[mi][1], Ah[mi][2], Ah[mi][3], Bh[2], Bh[3]); \
                MMA16816(c1, Ah[mi][0], Ah[mi][1], Ah[mi][2], Ah[mi][3], Bl[2], Bl[3]); \
                MMA16816(c1, Al[mi][0], Al[mi][1], Al[mi][2], Al[mi][3], Bh[2], Bh[3]); \
            }                                                              \
        }                                                                  \
    } while (0)

    // ---- prologue: chunks 0,1,2 -> slots 0,1,2; chunk 3 held ----
    LDG_CHUNK(0); STS_CHUNK(0);
    LDG_CHUNK(1); STS_CHUNK(1);
    LDG_CHUNK(2); STS_CHUNK(2);
    LDG_CHUNK(3);
    __syncthreads();

    // ---- main loop: 10 double-windows of 6 chunks (0..59 MMA'd) ----
    // Window A: MMA slots 0,1,2 while storing chunks 6i+3..5 -> slots 3,4,5.
    // Window B: MMA slots 3,4,5 while storing chunks 6i+6..8 -> slots 0,1,2.
    // All chunk indices stay < 64 for i <= 9; no guards needed.
    #pragma unroll 1
    for (int i = 0; i < 10; ++i) {
        // window A
        STS_CHUNK(3); LDG_CHUNK(6 * i + 4);
        MMA_SLOT(0);
        STS_CHUNK(4); LDG_CHUNK(6 * i + 5);
        MMA_SLOT(1);
        STS_CHUNK(5); LDG_CHUNK(6 * i + 6);
        MMA_SLOT(2);
        __syncthreads();
        // window B
        STS_CHUNK(0); LDG_CHUNK(6 * i + 7);
        MMA_SLOT(3);
        STS_CHUNK(1); LDG_CHUNK(6 * i + 8);
        MMA_SLOT(4);
        STS_CHUNK(2); LDG_CHUNK(6 * i + 9);
        MMA_SLOT(5);
        __syncthreads();
    }
    // ---- tail: chunks 60,61,62 are in slots 0,1,2; chunk 63 is held ----
    STS_CHUNK(3);                       // chunk 63 -> slot 3
    MMA_SLOT(0);
    MMA_SLOT(1);
    MMA_SLOT(2);
    __syncthreads();
    MMA_SLOT(3);                        // chunk 63

    // ---- epilogue: apply key mask, write C ----
    const float NEG_INF = __int_as_float(0xff800000);
    const int mrow = bm + wm * 32 + (lane >> 2);
    const int ncl  = wn * 64 + (lane & 3) * 2;
    #pragma unroll
    for (int mi = 0; mi < 2; ++mi) {
        #pragma unroll
        for (int ni = 0; ni < 8; ++ni) {
            const int nc = ncl + ni * 8;
            const float m0 = maskv[nc];
            const float m1 = maskv[nc + 1];
            const float* c = acc[mi][ni];
            float2 v0, v1;
            v0.x = (m0 != 0.0f) ? NEG_INF : c[0];
            v0.y = (m1 != 0.0f) ? NEG_INF : c[1];
            v1.x = (m0 != 0.0f) ? NEG_INF : c[2];
            v1.y = (m1 != 0.0f) ? NEG_INF : c[3];
            float* base = C + (size_t)(mrow + mi * 16) * KDIM + bn + nc;
            *(float2*)base              = v0;
            *(float2*)(base + 8 * KDIM) = v1;
        }
    }
    #undef LDG_CHUNK
    #undef STS_CHUNK
    #undef MMA_SLOT
}

// ---------------------------------------------------------------------------
// Softmax + confidence: one WARP per row (512 floats = 16 per lane).
// No block barriers; warp-shuffle reductions only.
// ---------------------------------------------------------------------------
__global__ __launch_bounds__(256)
void softmax_conf_kernel(const float* __restrict__ tptr,
                         const float* __restrict__ bptr,
                         float* __restrict__ out) {
    const int warp = threadIdx.x >> 5;
    const int lane = threadIdx.x & 31;
    const int row  = blockIdx.x * 8 + warp;          // b*Q + q
    float* lr = out + (size_t)row * KDIM;

    float4 v0 = *(const float4*)(lr + lane * 4);
    float4 v1 = *(const float4*)(lr + 128 + lane * 4);
    float4 v2 = *(const float4*)(lr + 256 + lane * 4);
    float4 v3 = *(const float4*)(lr + 384 + lane * 4);

    // --- max ---
    float m0 = fmaxf(fmaxf(v0.x, v0.y), fmaxf(v0.z, v0.w));
    float m1 = fmaxf(fmaxf(v1.x, v1.y), fmaxf(v1.z, v1.w));
    float m2 = fmaxf(fmaxf(v2.x, v2.y), fmaxf(v2.z, v2.w));
    float m3 = fmaxf(fmaxf(v3.x, v3.y), fmaxf(v3.z, v3.w));
    float m = fmaxf(fmaxf(m0, m1), fmaxf(m2, m3));
    #pragma unroll
    for (int o = 16; o > 0; o >>= 1)
        m = fmaxf(m, __shfl_xor_sync(0xffffffffu, m, o));

    // --- exp + sum ---  (exp(-inf - m) = 0 handles masked cols)
    float e[16];
    e[0]  = __expf(v0.x - m); e[1]  = __expf(v0.y - m);
    e[2]  = __expf(v0.z - m); e[3]  = __expf(v0.w - m);
    e[4]  = __expf(v1.x - m); e[5]  = __expf(v1.y - m);
    e[6]  = __expf(v1.z - m); e[7]  = __expf(v1.w - m);
    e[8]  = __expf(v2.x - m); e[9]  = __expf(v2.y - m);
    e[10] = __expf(v2.z - m); e[11] = __expf(v2.w - m);
    e[12] = __expf(v3.x - m); e[13] = __expf(v3.y - m);
    e[14] = __expf(v3.z - m); e[15] = __expf(v3.w - m);
    float s = 0.0f;
    #pragma unroll
    for (int i = 0; i < 16; ++i) s += e[i];
    #pragma unroll
    for (int o = 16; o > 0; o >>= 1)
        s += __shfl_xor_sync(0xffffffffu, s, o);

    const float inv = 1.0f / s;
    *(float4*)(lr + lane * 4)       = make_float4(e[0]*inv,  e[1]*inv,  e[2]*inv,  e[3]*inv);
    *(float4*)(lr + 128 + lane * 4) = make_float4(e[4]*inv,  e[5]*inv,  e[6]*inv,  e[7]*inv);
    *(float4*)(lr + 256 + lane * 4) = make_float4(e[8]*inv,  e[9]*inv,  e[10]*inv, e[11]*inv);
    *(float4*)(lr + 384 + lane * 4) = make_float4(e[12]*inv, e[13]*inv, e[14]*inv, e[15]*inv);

    if (lane == 0) {
        const float lse = m + logf(s);
        const float x = (lse + bptr[0]) * tptr[0];
        out[(size_t)BATCH * QDIM * KDIM + row] = 1.0f / (1.0f + __expf(-x));
    }
}

// ---------------------------------------------------------------------------
extern "C" void kernel_launch(void* const* d_in, const int* in_sizes, int n_in,
                              void* d_out, int out_size) {
    const float* q    = (const float*)d_in[0];
    const float* k    = (const float*)d_in[1];
    const float* temp = (const float*)d_in[2];
    const float* bias = (const float*)d_in[3];
    float* out = (float*)d_out;

    cudaFuncSetAttribute(gemm_bf16split_kernel,
                         cudaFuncAttributeMaxDynamicSharedMemorySize, SMEM_TOTAL);

    dim3 ggrid(KDIM / TN, QDIM / TM, BATCH);   // (4, 4, 32) = 512 CTAs
    gemm_bf16split_kernel<<<ggrid, 256, SMEM_TOTAL>>>(q, k, out);

    softmax_conf_kernel<<<BATCH * QDIM / 8, 256>>>(temp, bias, out);
}

// round 16
// speedup vs baseline: 1.1846x; 1.0009x over previous
#include <cuda_runtime.h>
#include <cuda_bf16.h>
#include <cstdint>

// Problem shape (fixed): B=32, Q=512, K=512, D=1024, fp32.
// Inputs: queries f32[B,Q,D], keys f32[B,K,D], temperature f32[], bias f32[]
// Output: attn f32[B,Q,K] then confidence f32[B,Q].
//
// GEMM (unchanged from R14 winner): error-free bf16 2-term split, 3 MMA
// products on mma.sync m16n8k16 — measured at the ~16 cyc/SMSP instruction
// issue floor; algorithmically and structurally converged.
// Softmax (this round): warp-per-row with tree-sum, fused ex2.approx, and
// .cs cache hints (logits dead after read; attn never re-read).

#define BATCH 32
#define QDIM 512
#define KDIM 512
#define DDIM 1024

#define TM 128
#define TN 128
#define NCHUNK 64                 // 64 chunks of k=16 floats

// Dynamic smem: 6 slots per operand tensor (4KB each slot)
#define SM_AH 0
#define SM_AL 24576
#define SM_BH 49152
#define SM_BL 73728
#define SM_MASK 98304
#define SMEM_TOTAL (98304 + 512)

// ---------------- PTX helpers ----------------
__device__ __forceinline__ uint32_t smem_u32(const void* p) {
    uint32_t a;
    asm("{ .reg .u64 t; cvta.to.shared.u64 t, %1; cvt.u32.u64 %0, t; }"
        : "=r"(a) : "l"(p));
    return a;
}

#define LDSM4(r0, r1, r2, r3, addr)                                        \
    asm volatile("ldmatrix.sync.aligned.m8n8.x4.shared.b16 "               \
                 "{%0, %1, %2, %3}, [%4];"                                 \
                 : "=r"(r0), "=r"(r1), "=r"(r2), "=r"(r3) : "r"(addr))

#define STS128(addr, r0, r1, r2, r3)                                       \
    asm volatile("st.shared.v4.b32 [%0], {%1, %2, %3, %4};"                \
                 :: "r"(addr), "r"(r0), "r"(r1), "r"(r2), "r"(r3) : "memory")

#define MMA16816(c, a0, a1, a2, a3, b0, b1)                                \
    asm volatile("mma.sync.aligned.m16n8k16.row.col.f32.bf16.bf16.f32 "    \
                 "{%0, %1, %2, %3}, {%4, %5, %6, %7}, {%8, %9}, "          \
                 "{%0, %1, %2, %3};"                                       \
                 : "+f"((c)[0]), "+f"((c)[1]), "+f"((c)[2]), "+f"((c)[3])  \
                 : "r"(a0), "r"(a1), "r"(a2), "r"(a3), "r"(b0), "r"(b1))

__device__ __forceinline__ void split2(float x, float y,
                                       uint32_t& h, uint32_t& l) {
    __nv_bfloat162 hh = __floats2bfloat162_rn(x, y);
    float rx = x - __bfloat162float(hh.x);
    float ry = y - __bfloat162float(hh.y);
    __nv_bfloat162 ll = __floats2bfloat162_rn(rx, ry);
    h = reinterpret_cast<uint32_t&>(hh);
    l = reinterpret_cast<uint32_t&>(ll);
}

// Swizzled byte offset: row r (0..127), 16-byte chunk c (0..1); 32B rows.
__device__ __forceinline__ uint32_t swz(int r, int c) {
    return (uint32_t)(r * 32 + ((c ^ ((r >> 2) & 1)) << 4));
}

// ---------------------------------------------------------------------------
// GEMM: logits = Q*K^T via 3x bf16 mma.sync split; key mask -> -inf.
// CTA 128x128, 256 threads, warps 4(M) x 2(N), warp tile 32x64.
// Ring-6 k16 slots, one barrier per 3 chunks, occupancy 2.  (R14 winner.)
// ---------------------------------------------------------------------------
__global__ __launch_bounds__(256, 2)
void gemm_bf16split_kernel(const float* __restrict__ Qg,
                           const float* __restrict__ Kg,
                           float* __restrict__ Cg) {
    extern __shared__ __align__(128) uint8_t smem[];
    const uint32_t sb = smem_u32(smem);
    float* maskv = (float*)(smem + SM_MASK);

    const int tid  = threadIdx.x;
    const int lane = tid & 31;
    const int wid  = tid >> 5;
    const int wm   = wid & 3;          // 0..3  (M)
    const int wn   = wid >> 2;         // 0..1  (N)

    const int bn = blockIdx.x * TN;
    const int bm = blockIdx.y * TM;
    const int b  = blockIdx.z;

    const float* A  = Qg + (size_t)b * QDIM * DDIM;
    const float* Bp = Kg + (size_t)b * KDIM * DDIM;
    float*       C  = Cg + (size_t)b * QDIM * KDIM;

    if (tid < TN)
        maskv[tid] = (Bp[(size_t)(bn + tid) * DDIM] == 0.0f) ? 1.0f : 0.0f;

    const int pr = tid >> 1;           // 0..127
    const int ph = tid & 1;
    const uint32_t so = swz(pr, ph);
    const uint32_t stAh = sb + SM_AH + so;
    const uint32_t stAl = sb + SM_AL + so;
    const uint32_t stBh = sb + SM_BH + so;
    const uint32_t stBl = sb + SM_BL + so;
    const float* gA = A  + (size_t)(bm + pr) * DDIM + ph * 8;
    const float* gB = Bp + (size_t)(bn + pr) * DDIM + ph * 8;

    uint32_t lmA, lmB;
    {
        int r = wm * 32 + (lane & 15);
        int c = lane >> 4;
        lmA = swz(r, c);
    }
    {
        int r = wn * 64 + (lane & 7) + ((lane >> 4) << 3);
        int c = (lane >> 3) & 1;
        lmB = swz(r, c);
    }
    const uint32_t aAh = sb + SM_AH + lmA;
    const uint32_t aAl = sb + SM_AL + lmA;
    const uint32_t aBh = sb + SM_BH + lmB;
    const uint32_t aBl = sb + SM_BL + lmB;

    float acc[2][8][4];
    #pragma unroll
    for (int i = 0; i < 2; ++i)
        #pragma unroll
        for (int j = 0; j < 8; ++j)
            #pragma unroll
            for (int k = 0; k < 4; ++k) acc[i][j][k] = 0.0f;

    float4 va0, va1, vb0, vb1;         // the single held prefetch set

    #define LDG_CHUNK(c) do {                                              \
        const float* _pa = gA + (c) * 16;                                  \
        const float* _pb = gB + (c) * 16;                                  \
        va0 = *(const float4*)_pa;  va1 = *(const float4*)(_pa + 4);       \
        vb0 = *(const float4*)_pb;  vb1 = *(const float4*)(_pb + 4);       \
    } while (0)

    #define STS_CHUNK(q) do {                                              \
        const uint32_t _o = (uint32_t)(q) * 4096u;                         \
        uint32_t h0, h1, h2, h3, l0, l1, l2, l3;                           \
        split2(va0.x, va0.y, h0, l0); split2(va0.z, va0.w, h1, l1);        \
        split2(va1.x, va1.y, h2, l2); split2(va1.z, va1.w, h3, l3);        \
        STS128(stAh + _o, h0, h1, h2, h3);                                 \
        STS128(stAl + _o, l0, l1, l2, l3);                                 \
        split2(vb0.x, vb0.y, h0, l0); split2(vb0.z, vb0.w, h1, l1);        \
        split2(vb1.x, vb1.y, h2, l2); split2(vb1.z, vb1.w, h3, l3);        \
        STS128(stBh + _o, h0, h1, h2, h3);                                 \
        STS128(stBl + _o, l0, l1, l2, l3);                                 \
    } while (0)

    #define MMA_SLOT(q) do {                                               \
        const uint32_t _o = (uint32_t)(q) * 4096u;                         \
        uint32_t Ah[2][4], Al[2][4];                                       \
        LDSM4(Ah[0][0], Ah[0][1], Ah[0][2], Ah[0][3], aAh + _o);           \
        LDSM4(Ah[1][0], Ah[1][1], Ah[1][2], Ah[1][3], aAh + _o + 512);     \
        LDSM4(Al[0][0], Al[0][1], Al[0][2], Al[0][3], aAl + _o);           \
        LDSM4(Al[1][0], Al[1][1], Al[1][2], Al[1][3], aAl + _o + 512);     \
        _Pragma("unroll")                                                  \
        for (int q4 = 0; q4 < 4; ++q4) {                                   \
            uint32_t Bh[4], Bl[4];                                         \
            LDSM4(Bh[0], Bh[1], Bh[2], Bh[3], aBh + _o + q4 * 512);        \
            LDSM4(Bl[0], Bl[1], Bl[2], Bl[3], aBl + _o + q4 * 512);        \
            _Pragma("unroll")                                              \
            for (int mi = 0; mi < 2; ++mi) {                               \
                float* c0 = acc[mi][2 * q4];                               \
                float* c1 = acc[mi][2 * q4 + 1];                           \
                MMA16816(c0, Ah[mi][0], Ah[mi][1], Ah[mi][2], Ah[mi][3], Bh[0], Bh[1]); \
                MMA16816(c0, Ah[mi][0], Ah[mi][1], Ah[mi][2], Ah[mi][3], Bl[0], Bl[1]); \
                MMA16816(c0, Al[mi][0], Al[mi][1], Al[mi][2], Al[mi][3], Bh[0], Bh[1]); \
                MMA16816(c1, Ah[mi][0], Ah[mi][1], Ah[mi][2], Ah[mi][3], Bh[2], Bh[3]); \
                MMA16816(c1, Ah[mi][0], Ah[mi][1], Ah[mi][2], Ah[mi][3], Bl[2], Bl[3]); \
                MMA16816(c1, Al[mi][0], Al[mi][1], Al[mi][2], Al[mi][3], Bh[2], Bh[3]); \
            }                                                              \
        }                                                                  \
    } while (0)

    LDG_CHUNK(0); STS_CHUNK(0);
    LDG_CHUNK(1); STS_CHUNK(1);
    LDG_CHUNK(2); STS_CHUNK(2);
    LDG_CHUNK(3);
    __syncthreads();

    #pragma unroll 1
    for (int i = 0; i < 10; ++i) {
        STS_CHUNK(3); LDG_CHUNK(6 * i + 4);
        MMA_SLOT(0);
        STS_CHUNK(4); LDG_CHUNK(6 * i + 5);
        MMA_SLOT(1);
        STS_CHUNK(5); LDG_CHUNK(6 * i + 6);
        MMA_SLOT(2);
        __syncthreads();
        STS_CHUNK(0); LDG_CHUNK(6 * i + 7);
        MMA_SLOT(3);
        STS_CHUNK(1); LDG_CHUNK(6 * i + 8);
        MMA_SLOT(4);
        STS_CHUNK(2); LDG_CHUNK(6 * i + 9);
        MMA_SLOT(5);
        __syncthreads();
    }
    STS_CHUNK(3);                       // chunk 63 -> slot 3
    MMA_SLOT(0);
    MMA_SLOT(1);
    MMA_SLOT(2);
    __syncthreads();
    MMA_SLOT(3);                        // chunk 63

    const float NEG_INF = __int_as_float(0xff800000);
    const int mrow = bm + wm * 32 + (lane >> 2);
    const int ncl  = wn * 64 + (lane & 3) * 2;
    #pragma unroll
    for (int mi = 0; mi < 2; ++mi) {
        #pragma unroll
        for (int ni = 0; ni < 8; ++ni) {
            const int nc = ncl + ni * 8;
            const float m0 = maskv[nc];
            const float m1 = maskv[nc + 1];
            const float* c = acc[mi][ni];
            float2 v0, v1;
            v0.x = (m0 != 0.0f) ? NEG_INF : c[0];
            v0.y = (m1 != 0.0f) ? NEG_INF : c[1];
            v1.x = (m0 != 0.0f) ? NEG_INF : c[2];
            v1.y = (m1 != 0.0f) ? NEG_INF : c[3];
            float* base = C + (size_t)(mrow + mi * 16) * KDIM + bn + nc;
            *(float2*)base              = v0;
            *(float2*)(base + 8 * KDIM) = v1;
        }
    }
    #undef LDG_CHUNK
    #undef STS_CHUNK
    #undef MMA_SLOT
}

// ---------------------------------------------------------------------------
// Softmax + confidence: one WARP per row (512 floats = 16 per lane).
// Tree reductions, fused ex2.approx, .cs load/store hints.
// ---------------------------------------------------------------------------
__device__ __forceinline__ float4 ldg_cs4(const float* p) {
    float4 v;
    asm volatile("ld.global.cs.v4.f32 {%0, %1, %2, %3}, [%4];"
                 : "=f"(v.x), "=f"(v.y), "=f"(v.z), "=f"(v.w) : "l"(p));
    return v;
}
__device__ __forceinline__ void stg_cs4(float* p, float4 v) {
    asm volatile("st.global.cs.v4.f32 [%0], {%1, %2, %3, %4};"
                 :: "l"(p), "f"(v.x), "f"(v.y), "f"(v.z), "f"(v.w) : "memory");
}
__device__ __forceinline__ float ex2f(float x) {
    float r;
    asm("ex2.approx.ftz.f32 %0, %1;" : "=f"(r) : "f"(x));
    return r;
}

__global__ __launch_bounds__(256)
void softmax_conf_kernel(const float* __restrict__ tptr,
                         const float* __restrict__ bptr,
                         float* __restrict__ out) {
    const int warp = threadIdx.x >> 5;
    const int lane = threadIdx.x & 31;
    const int row  = blockIdx.x * 8 + warp;          // b*Q + q
    float* lr = out + (size_t)row * KDIM;

    float4 v0 = ldg_cs4(lr + lane * 4);
    float4 v1 = ldg_cs4(lr + 128 + lane * 4);
    float4 v2 = ldg_cs4(lr + 256 + lane * 4);
    float4 v3 = ldg_cs4(lr + 384 + lane * 4);

    // --- max (tree) ---
    float m0 = fmaxf(fmaxf(v0.x, v0.y), fmaxf(v0.z, v0.w));
    float m1 = fmaxf(fmaxf(v1.x, v1.y), fmaxf(v1.z, v1.w));
    float m2 = fmaxf(fmaxf(v2.x, v2.y), fmaxf(v2.z, v2.w));
    float m3 = fmaxf(fmaxf(v3.x, v3.y), fmaxf(v3.z, v3.w));
    float m = fmaxf(fmaxf(m0, m1), fmaxf(m2, m3));
    #pragma unroll
    for (int o = 16; o > 0; o >>= 1)
        m = fmaxf(m, __shfl_xor_sync(0xffffffffu, m, o));

    // --- exp2((v - m) * log2e) : one FMA + one MUFU per element ---
    const float L2E = 1.4426950408889634f;
    const float nm  = -m * L2E;
    float e[16];
    e[0]  = ex2f(fmaf(v0.x, L2E, nm)); e[1]  = ex2f(fmaf(v0.y, L2E, nm));
    e[2]  = ex2f(fmaf(v0.z, L2E, nm)); e[3]  = ex2f(fmaf(v0.w, L2E, nm));
    e[4]  = ex2f(fmaf(v1.x, L2E, nm)); e[5]  = ex2f(fmaf(v1.y, L2E, nm));
    e[6]  = ex2f(fmaf(v1.z, L2E, nm)); e[7]  = ex2f(fmaf(v1.w, L2E, nm));
    e[8]  = ex2f(fmaf(v2.x, L2E, nm)); e[9]  = ex2f(fmaf(v2.y, L2E, nm));
    e[10] = ex2f(fmaf(v2.z, L2E, nm)); e[11] = ex2f(fmaf(v2.w, L2E, nm));
    e[12] = ex2f(fmaf(v3.x, L2E, nm)); e[13] = ex2f(fmaf(v3.y, L2E, nm));
    e[14] = ex2f(fmaf(v3.z, L2E, nm)); e[15] = ex2f(fmaf(v3.w, L2E, nm));

    // --- sum (depth-4 tree) ---
    float t0 = (e[0] + e[1])  + (e[2] + e[3]);
    float t1 = (e[4] + e[5])  + (e[6] + e[7]);
    float t2 = (e[8] + e[9])  + (e[10] + e[11]);
    float t3 = (e[12] + e[13]) + (e[14] + e[15]);
    float s = (t0 + t1) + (t2 + t3);
    #pragma unroll
    for (int o = 16; o > 0; o >>= 1)
        s += __shfl_xor_sync(0xffffffffu, s, o);

    const float inv = 1.0f / s;
    stg_cs4(lr + lane * 4,       make_float4(e[0]*inv,  e[1]*inv,  e[2]*inv,  e[3]*inv));
    stg_cs4(lr + 128 + lane * 4, make_float4(e[4]*inv,  e[5]*inv,  e[6]*inv,  e[7]*inv));
    stg_cs4(lr + 256 + lane * 4, make_float4(e[8]*inv,  e[9]*inv,  e[10]*inv, e[11]*inv));
    stg_cs4(lr + 384 + lane * 4, make_float4(e[12]*inv, e[13]*inv, e[14]*inv, e[15]*inv));

    if (lane == 0) {
        const float lse = m + logf(s);
        const float x = (lse + bptr[0]) * tptr[0];
        out[(size_t)BATCH * QDIM * KDIM + row] = 1.0f / (1.0f + __expf(-x));
    }
}

// ---------------------------------------------------------------------------
extern "C" void kernel_launch(void* const* d_in, const int* in_sizes, int n_in,
                              void* d_out, int out_size) {
    const float* q    = (const float*)d_in[0];
    const float* k    = (const float*)d_in[1];
    const float* temp = (const float*)d_in[2];
    const float* bias = (const float*)d_in[3];
    float* out = (float*)d_out;

    cudaFuncSetAttribute(gemm_bf16split_kernel,
                         cudaFuncAttributeMaxDynamicSharedMemorySize, SMEM_TOTAL);

    dim3 ggrid(KDIM / TN, QDIM / TM, BATCH);   // (4, 4, 32) = 512 CTAs
    gemm_bf16split_kernel<<<ggrid, 256, SMEM_TOTAL>>>(q, k, out);

    softmax_conf_kernel<<<BATCH * QDIM / 8, 256>>>(temp, bias, out);
}